// round 1
// baseline (speedup 1.0000x reference)
#include <cuda_runtime.h>

// FOG: stride-2 occupancy downsample of 4M sparse voxels.
// Bitmap over the 2^29 key space replaces sort/unique:
//   rank(key) = popcount of set bits below key  (== index in sorted unique list)

#define HALF 512
#define NWORDS (1u << 23)            // 2^29 keys / 64 bits per word
#define SCAN_T 256
#define SCAN_I 8
#define SCAN_CHUNK (SCAN_T * SCAN_I) // 2048 words per scan block
#define NB_SCAN (NWORDS / SCAN_CHUNK) // 4096
#define MAXN 4000000

__device__ unsigned long long g_bits[NWORDS];    // 64 MB occupancy bitmap
__device__ unsigned int       g_prefix[NWORDS];  // 32 MB exclusive popcount prefix
__device__ unsigned int       g_packed[MAXN];    // 16 MB per-point (key<<3)|off
__device__ unsigned int       g_blocksums[NB_SCAN];
__device__ unsigned int       g_total;

// ---- pass A: key/off per point, mark bitmap -------------------------------
__global__ void kA(const int4* __restrict__ coords, int n) {
    int i = blockIdx.x * blockDim.x + threadIdx.x;
    if (i >= n) return;
    int4 c = coords[i];  // {b, x, y, z}
    unsigned off = (unsigned)((c.y & 1) | ((c.z & 1) << 1) | ((c.w & 1) << 2));
    unsigned key = (((unsigned)c.x * HALF + (unsigned)(c.w >> 1)) * HALF
                    + (unsigned)(c.z >> 1)) * HALF + (unsigned)(c.y >> 1);
    g_packed[i] = (key << 3) | off;
    atomicOr(&g_bits[key >> 6], 1ull << (key & 63));
}

// ---- scan phase 1: per-block popcount sums --------------------------------
__global__ void kP1() {
    unsigned base = blockIdx.x * SCAN_CHUNK + threadIdx.x * SCAN_I;
    unsigned s = 0;
#pragma unroll
    for (int j = 0; j < SCAN_I; j++) s += (unsigned)__popcll(g_bits[base + j]);
    __shared__ unsigned sh[SCAN_T];
    sh[threadIdx.x] = s;
    __syncthreads();
    for (int off = SCAN_T / 2; off > 0; off >>= 1) {
        if (threadIdx.x < off) sh[threadIdx.x] += sh[threadIdx.x + off];
        __syncthreads();
    }
    if (threadIdx.x == 0) g_blocksums[blockIdx.x] = sh[0];
}

// ---- scan phase 2: exclusive scan of 4096 block sums (one block) ----------
__global__ void kP2() {
    __shared__ unsigned sh[1024];
    unsigned tid = threadIdx.x;
    unsigned v[4];
    unsigned base = tid * 4;
    unsigned t = 0;
#pragma unroll
    for (int j = 0; j < 4; j++) { v[j] = g_blocksums[base + j]; t += v[j]; }
    sh[tid] = t;
    __syncthreads();
    for (int off = 1; off < 1024; off <<= 1) {
        unsigned x = (tid >= (unsigned)off) ? sh[tid - off] : 0u;
        __syncthreads();
        sh[tid] += x;
        __syncthreads();
    }
    unsigned run = sh[tid] - t;  // exclusive
#pragma unroll
    for (int j = 0; j < 4; j++) { unsigned old = v[j]; g_blocksums[base + j] = run; run += old; }
    if (tid == 1023) g_total = run;
}

// ---- scan phase 3: per-word exclusive prefix ------------------------------
__global__ void kP3() {
    unsigned base = blockIdx.x * SCAN_CHUNK + threadIdx.x * SCAN_I;
    unsigned p[SCAN_I];
    unsigned s = 0;
#pragma unroll
    for (int j = 0; j < SCAN_I; j++) { p[j] = (unsigned)__popcll(g_bits[base + j]); s += p[j]; }
    __shared__ unsigned sh[SCAN_T];
    unsigned tid = threadIdx.x;
    sh[tid] = s;
    __syncthreads();
    for (int off = 1; off < SCAN_T; off <<= 1) {
        unsigned x = (tid >= (unsigned)off) ? sh[tid - off] : 0u;
        __syncthreads();
        sh[tid] += x;
        __syncthreads();
    }
    unsigned run = sh[tid] - s + g_blocksums[blockIdx.x];
#pragma unroll
    for (int j = 0; j < SCAN_I; j++) { g_prefix[base + j] = run; run += p[j]; }
}

// ---- pass B: scatter-add contribs into feats by rank ----------------------
__global__ void kB(const float* __restrict__ kw, float* __restrict__ feats, int n) {
    int i = blockIdx.x * blockDim.x + threadIdx.x;
    if (i >= n) return;
    unsigned p = g_packed[i];
    unsigned key = p >> 3;
    unsigned off = p & 7u;
    unsigned w = key >> 6;
    unsigned b = key & 63u;
    unsigned long long word = g_bits[w];
    unsigned rank = g_prefix[w] + (unsigned)__popcll(word & ((1ull << b) - 1ull));
    float contrib = (float)(1u << off) * __ldg(&kw[off]);
    atomicAdd(&feats[rank], contrib);
}

// ---- pass C: compact sorted unique coords ---------------------------------
__global__ void kC(float4* __restrict__ cout) {
    unsigned w = blockIdx.x * blockDim.x + threadIdx.x;
    if (w >= NWORDS) return;
    unsigned long long word = g_bits[w];
    if (!word) return;
    unsigned rank = g_prefix[w];
    unsigned keybase = w << 6;
    while (word) {
        unsigned b = (unsigned)__ffsll((long long)word) - 1u;
        word &= word - 1ull;
        unsigned key = keybase + b;
        float px = (float)(key & 511u);
        float py = (float)((key >> 9) & 511u);
        float pz = (float)((key >> 18) & 511u);
        float pb = (float)(key >> 27);
        cout[rank++] = make_float4(pb, px, py, pz);
    }
}

// ---- pass D: fill padding slots with -1 -----------------------------------
__global__ void kD(float4* __restrict__ cout, int n) {
    unsigned i = blockIdx.x * blockDim.x + threadIdx.x;
    if (i >= (unsigned)n) return;
    if (i >= g_total) cout[i] = make_float4(-1.f, -1.f, -1.f, -1.f);
}

// ---- pass E: clear bitmap for next replay ---------------------------------
__global__ void kE() {
    unsigned i = blockIdx.x * blockDim.x + threadIdx.x;  // NWORDS/2 ulonglong2
    reinterpret_cast<ulonglong2*>(g_bits)[i] = make_ulonglong2(0ull, 0ull);
}

extern "C" void kernel_launch(void* const* d_in, const int* in_sizes, int n_in,
                              void* d_out, int out_size) {
    const int4*  coords = (const int4*)d_in[0];
    const float* kw     = (const float*)d_in[1];
    float* out = (float*)d_out;
    int n = in_sizes[0] / 4;                 // number of points
    float* feats = out + (size_t)4 * n;      // layout: coords (N,4) then feats (N,1)

    cudaMemsetAsync(feats, 0, (size_t)n * sizeof(float), 0);

    const int TB = 256;
    int nb = (n + TB - 1) / TB;
    kA<<<nb, TB>>>(coords, n);
    kP1<<<NB_SCAN, SCAN_T>>>();
    kP2<<<1, 1024>>>();
    kP3<<<NB_SCAN, SCAN_T>>>();
    kB<<<nb, TB>>>(kw, feats, n);
    kC<<<(NWORDS + TB - 1) / TB, TB>>>((float4*)out);
    kD<<<nb, TB>>>((float4*)out, n);
    kE<<<(NWORDS / 2) / TB, TB>>>();
}

// round 2
// speedup vs baseline: 1.5738x; 1.5738x over previous
#include <cuda_runtime.h>

// FOG: stride-2 occupancy downsample of 4M sparse voxels.
// Bitmap over the 2^29 key space replaces sort/unique:
//   rank(key) = popcount of set bits below key (== index in sorted unique list)
// Single-pass decoupled-lookback scan fuses prefix computation with the
// compacted coords write; prefix stored per 4-word group (one 32B sector).

#define HALF 512
#define NWORDS (1u << 23)             // 2^29 keys / 64 bits per word
#define TILE_T 512
#define TILE_I 8
#define TILE_WORDS (TILE_T * TILE_I)  // 4096 words per tile
#define NTILES (NWORDS / TILE_WORDS)  // 2048
#define MAXN 4000000

__device__ unsigned long long g_bits[NWORDS];       // 64 MB occupancy bitmap
__device__ unsigned int       g_prefix4[NWORDS/4];  // 8.4 MB: rank at each 4-word group
__device__ unsigned int       g_packed[MAXN];       // 16 MB per-point (key<<3)|off
__device__ unsigned int       g_status[NTILES];     // lookback: (val<<2)|flag (1=agg,2=inc)
__device__ unsigned int       g_ticket;
__device__ unsigned int       g_total;

// ---- pass A: key/off per point, mark bitmap -------------------------------
__global__ void kA(const int4* __restrict__ coords, int n) {
    int i = blockIdx.x * blockDim.x + threadIdx.x;
    if (i >= n) return;
    int4 c = __ldcs(&coords[i]);  // {b, x, y, z}, streaming (no reuse)
    unsigned off = (unsigned)((c.y & 1) | ((c.z & 1) << 1) | ((c.w & 1) << 2));
    unsigned key = (((unsigned)c.x * HALF + (unsigned)(c.w >> 1)) * HALF
                    + (unsigned)(c.z >> 1)) * HALF + (unsigned)(c.y >> 1);
    g_packed[i] = (key << 3) | off;
    atomicOr(&g_bits[key >> 6], 1ull << (key & 63));
}

// ---- fused scan + compact: decoupled lookback -----------------------------
__global__ void __launch_bounds__(TILE_T) kScan(float4* __restrict__ cout) {
    __shared__ unsigned s_tile;
    __shared__ unsigned s_warpsum[TILE_T / 32];
    __shared__ unsigned s_excl;

    if (threadIdx.x == 0) s_tile = atomicAdd(&g_ticket, 1u);
    __syncthreads();
    const unsigned tile = s_tile;
    const unsigned base = tile * TILE_WORDS + threadIdx.x * TILE_I;

    unsigned long long words[TILE_I];
    {
        const ulonglong2* p = reinterpret_cast<const ulonglong2*>(&g_bits[base]);
#pragma unroll
        for (int j = 0; j < TILE_I / 2; j++) {
            ulonglong2 v = p[j];
            words[2 * j] = v.x; words[2 * j + 1] = v.y;
        }
    }
    unsigned pc[TILE_I], s = 0;
#pragma unroll
    for (int j = 0; j < TILE_I; j++) { pc[j] = (unsigned)__popcll(words[j]); s += pc[j]; }

    // block-wide exclusive scan of per-thread sums
    const unsigned lane = threadIdx.x & 31u, wid = threadIdx.x >> 5;
    unsigned inc = s;
#pragma unroll
    for (int d = 1; d < 32; d <<= 1) {
        unsigned x = __shfl_up_sync(0xffffffffu, inc, d);
        if (lane >= (unsigned)d) inc += x;
    }
    if (lane == 31) s_warpsum[wid] = inc;
    __syncthreads();
    if (threadIdx.x < TILE_T / 32) {
        unsigned v = s_warpsum[threadIdx.x];
#pragma unroll
        for (int d = 1; d < TILE_T / 32; d <<= 1) {
            unsigned x = __shfl_up_sync((1u << (TILE_T / 32)) - 1u, v, d);
            if (threadIdx.x >= (unsigned)d) v += x;
        }
        s_warpsum[threadIdx.x] = v;
    }
    __syncthreads();
    const unsigned wordExcl = (wid ? s_warpsum[wid - 1] : 0u) + (inc - s);
    const unsigned tileAgg  = s_warpsum[TILE_T / 32 - 1];

    // publish aggregate (or inclusive for tile 0) ASAP
    if (threadIdx.x == 0) {
        if (tile == 0) {
            atomicExch(&g_status[0], (tileAgg << 2) | 2u);
            s_excl = 0u;
            if (NTILES == 1) g_total = tileAgg;
        } else {
            atomicExch(&g_status[tile], (tileAgg << 2) | 1u);
        }
    }

    // warp 0: decoupled lookback
    if (wid == 0 && tile > 0) {
        unsigned excl = 0;
        int look = (int)tile - 1;
        for (;;) {
            int idx = look - (int)lane;
            unsigned stv;
            do {
                stv = (idx >= 0) ? *(volatile unsigned*)&g_status[idx] : 2u;
            } while (__any_sync(0xffffffffu, (stv & 3u) == 0u));
            unsigned incMask = __ballot_sync(0xffffffffu, (stv & 3u) == 2u);
            if (incMask) {
                int firstInc = __ffs(incMask) - 1;
                unsigned contrib = (lane <= (unsigned)firstInc && idx >= 0) ? (stv >> 2) : 0u;
#pragma unroll
                for (int d = 16; d; d >>= 1) contrib += __shfl_down_sync(0xffffffffu, contrib, d);
                excl += __shfl_sync(0xffffffffu, contrib, 0);
                break;
            } else {
                unsigned contrib = (idx >= 0) ? (stv >> 2) : 0u;
#pragma unroll
                for (int d = 16; d; d >>= 1) contrib += __shfl_down_sync(0xffffffffu, contrib, d);
                excl += __shfl_sync(0xffffffffu, contrib, 0);
                look -= 32;
            }
        }
        if (lane == 0) {
            atomicExch(&g_status[tile], ((excl + tileAgg) << 2) | 2u);
            s_excl = excl;
            if (tile == NTILES - 1) g_total = excl + tileAgg;
        }
    }
    __syncthreads();

    unsigned rank = s_excl + wordExcl;

    // per-4-word prefix (TILE_I==8 -> two groups per thread, coalesced)
    {
        unsigned g4 = base >> 2;
        g_prefix4[g4]     = rank;
        g_prefix4[g4 + 1] = rank + pc[0] + pc[1] + pc[2] + pc[3];
    }

    // emit compacted sorted coords
    unsigned r = rank;
#pragma unroll
    for (int j = 0; j < TILE_I; j++) {
        unsigned long long word = words[j];
        unsigned keybase = (base + j) << 6;
        while (word) {
            unsigned b = (unsigned)__ffsll((long long)word) - 1u;
            word &= word - 1ull;
            unsigned key = keybase + b;
            float4 v = make_float4((float)(key >> 27),
                                   (float)(key & 511u),
                                   (float)((key >> 9) & 511u),
                                   (float)((key >> 18) & 511u));
            __stcs(&cout[r], v);
            r++;
        }
    }
}

// ---- pass B: scatter-add contribs by rank + pad tail with -1 --------------
__global__ void kB(const float* __restrict__ kw, float* __restrict__ feats,
                   float4* __restrict__ cout, int n) {
    int i = blockIdx.x * blockDim.x + threadIdx.x;
    if (i >= n) return;
    unsigned p = g_packed[i];
    unsigned key = p >> 3;
    unsigned off = p & 7u;
    unsigned w = key >> 6;
    unsigned b = key & 63u;
    unsigned g4 = w >> 2;
    const ulonglong2* gp = reinterpret_cast<const ulonglong2*>(&g_bits[g4 << 2]);
    ulonglong2 lo = __ldg(gp);
    ulonglong2 hi = __ldg(gp + 1);
    unsigned long long ws0 = lo.x, ws1 = lo.y, ws2 = hi.x, ws3 = hi.y;
    unsigned wi = w & 3u;
    unsigned r = __ldg(&g_prefix4[g4]);
    if (wi > 0) r += (unsigned)__popcll(ws0);
    if (wi > 1) r += (unsigned)__popcll(ws1);
    if (wi > 2) r += (unsigned)__popcll(ws2);
    unsigned long long wsel = (wi == 0) ? ws0 : (wi == 1) ? ws1 : (wi == 2) ? ws2 : ws3;
    r += (unsigned)__popcll(wsel & ((1ull << b) - 1ull));
    float contrib = (float)(1u << off) * __ldg(&kw[off]);
    atomicAdd(&feats[r], contrib);
    // pad tail of coords output
    if ((unsigned)i >= g_total)
        __stcs(&cout[i], make_float4(-1.f, -1.f, -1.f, -1.f));
}

// ---- pass E: clear bitmap + lookback state for next replay ----------------
__global__ void kE() {
    unsigned i = blockIdx.x * blockDim.x + threadIdx.x;  // NWORDS/2 ulonglong2
    reinterpret_cast<ulonglong2*>(g_bits)[i] = make_ulonglong2(0ull, 0ull);
    if (i < NTILES) g_status[i] = 0u;
    if (i == 0) g_ticket = 0u;
}

extern "C" void kernel_launch(void* const* d_in, const int* in_sizes, int n_in,
                              void* d_out, int out_size) {
    const int4*  coords = (const int4*)d_in[0];
    const float* kw     = (const float*)d_in[1];
    float* out = (float*)d_out;
    int n = in_sizes[0] / 4;                 // number of points
    float* feats = out + (size_t)4 * n;      // layout: coords (N,4) then feats (N,1)

    cudaMemsetAsync(feats, 0, (size_t)n * sizeof(float), 0);

    const int TB = 256;
    int nb = (n + TB - 1) / TB;
    kA<<<nb, TB>>>(coords, n);
    kScan<<<NTILES, TILE_T>>>((float4*)out);
    kB<<<nb, TB>>>(kw, feats, (float4*)out, n);
    kE<<<(NWORDS / 2) / TB, TB>>>();
}